// round 7
// baseline (speedup 1.0000x reference)
#include <cuda_runtime.h>
#include <cstdint>

// Problem shape (fixed by the reference): N=1e6 rows, M=2e6 values, D=128 fp32.
#define ROW_F4 32              // 128 floats = 32 float4 per row
#define MAX_N  1000001         // N + 1 slots for segment starts

// Static scratch (no allocations allowed anywhere).
__device__ int g_row_start[MAX_N + 1];
__device__ int g_is64;         // 1 if sorted_indices is int64, 0 if int32

// Kernel 0: single thread detects the index dtype. We may only trust the
// first M int32 slots of the buffer (valid under both layouts). Under an
// int64 little-endian layout, the int32 view near slot M-1 alternates
// [value, 0, value, 0, ...] with value ~ N/2 -> sortedness violations.
// Under a true int32 layout the view is sorted -> no violations.
__global__ void detect_dtype_kernel(const int* __restrict__ idx32, int M) {
    int bad = 0;
    int start = M > 128 ? M - 128 : 0;
    for (int j = start; j + 1 < M; ++j)
        if (idx32[j] > idx32[j + 1]) bad = 1;
    g_is64 = bad;
}

// Kernel 1: one thread per row (plus sentinel) does lower_bound over the
// sorted index array, branching on detected dtype. Index array (8 or 16 MB)
// is L2-resident; adjacent threads share the upper tree levels.
__global__ void build_starts_kernel(const void* __restrict__ idx,
                                    int N, int M) {
    int t = blockIdx.x * blockDim.x + threadIdx.x;
    if (t > N) return;
    int lo = 0, hi = M;
    if (g_is64) {
        const long long* p = (const long long*)idx;
        long long target = (long long)t;
        while (lo < hi) {
            int mid = (lo + hi) >> 1;
            if (__ldg(p + mid) < target) lo = mid + 1;
            else                          hi = mid;
        }
    } else {
        const int* p = (const int*)idx;
        while (lo < hi) {
            int mid = (lo + hi) >> 1;
            if (__ldg(p + mid) < t) lo = mid + 1;
            else                    hi = mid;
        }
    }
    g_row_start[t] = lo;
}

// Kernel 2: one warp per output row. Each lane owns one float4 (16 B) of the
// 512 B row: acc = var[row]; add the avg ~2 contiguous value rows of this
// row's segment; store. Fully coalesced 128 B/warp streams -> HBM-bound.
__global__ void seg_add_kernel(const float4* __restrict__ var,
                               const float4* __restrict__ value,
                               float4* __restrict__ out,
                               int N) {
    int warp = (int)((blockIdx.x * (unsigned)blockDim.x + threadIdx.x) >> 5);
    int lane = threadIdx.x & 31;
    if (warp >= N) return;

    int s = g_row_start[warp];
    int e = g_row_start[warp + 1];

    size_t row_off = (size_t)warp * ROW_F4 + lane;
    float4 acc = __ldg(var + row_off);

    size_t voff = (size_t)s * ROW_F4 + lane;
    for (int m = s; m < e; ++m, voff += ROW_F4) {
        float4 v = __ldg(value + voff);
        acc.x += v.x; acc.y += v.y; acc.z += v.z; acc.w += v.w;
    }
    out[row_off] = acc;
}

extern "C" void kernel_launch(void* const* d_in, const int* in_sizes, int n_in,
                              void* d_out, int out_size) {
    const float* var   = (const float*)d_in[0];   // [N, 128] f32
    const float* value = (const float*)d_in[1];   // [M, 128] f32
    const void*  sidx  = d_in[2];                 // [M] int32 or int64, sorted
    // d_in[3] = pos (unused by the math)

    int N = in_sizes[0] / 128;
    int M = in_sizes[2];
    float* out = (float*)d_out;

    // Kernel 0: dtype detection (1 thread)
    detect_dtype_kernel<<<1, 1>>>((const int*)sidx, M);

    // Kernel 1: segment starts (N+1 threads)
    {
        int threads = 256;
        int total = N + 1;
        int blocks = (total + threads - 1) / threads;
        build_starts_kernel<<<blocks, threads>>>(sidx, N, M);
    }

    // Kernel 2: one warp per row
    {
        int threads = 256;                       // 8 warps -> 8 rows per block
        long long total_threads = (long long)N * 32;
        int blocks = (int)((total_threads + threads - 1) / threads);
        seg_add_kernel<<<blocks, threads>>>((const float4*)var,
                                            (const float4*)value,
                                            (float4*)out, N);
    }
}